// round 2
// baseline (speedup 1.0000x reference)
#include <cuda_runtime.h>
#include <cuda_bf16.h>
#include <math.h>

// Problem constants (match reference setup_inputs)
#define NN 100000      // nodes
#define NE 1600000     // edges
#define CH 128         // channels (in == hid)

// ---------------- scratch (no allocations allowed) ----------------
__device__ float g_agg[(size_t)NN * CH];
__device__ float g_h  [(size_t)NN * CH];
__device__ float g_z  [(size_t)NN * CH];
__device__ float g_inv[NN];
__device__ int   g_deg[NN];
__device__ int   g_cur[NN];
__device__ int   g_off[NN + 1];
__device__ int   g_csr_src[NE];
__device__ float g_csr_w[NE];

// ---------------- zero degree/cursor ----------------
__global__ void zero_deg_kernel(int n) {
    int i = blockIdx.x * blockDim.x + threadIdx.x;
    int stride = gridDim.x * blockDim.x;
    for (; i < n; i += stride) { g_deg[i] = 0; g_cur[i] = 0; }
}

// ---------------- histogram of in-degrees ----------------
__global__ void hist_kernel(const int* __restrict__ dst, int E) {
    int i = blockIdx.x * blockDim.x + threadIdx.x;
    int stride = gridDim.x * blockDim.x;
    for (; i < E; i += stride) atomicAdd(&g_deg[dst[i]], 1);
}

// ---------------- single-block exclusive scan -> offsets, inv degree ----------------
__global__ __launch_bounds__(1024) void scan_kernel(int N, int E) {
    __shared__ int sums[1024];
    int t = threadIdx.x;
    int chunk = (N + 1023) >> 10;
    int lo = t * chunk;
    int hi = min(lo + chunk, N);
    int s = 0;
    for (int i = lo; i < hi; i++) s += g_deg[i];
    sums[t] = s;
    __syncthreads();
    // Hillis-Steele inclusive scan
    for (int o = 1; o < 1024; o <<= 1) {
        int v = (t >= o) ? sums[t - o] : 0;
        __syncthreads();
        sums[t] += v;
        __syncthreads();
    }
    int run = (t > 0) ? sums[t - 1] : 0;
    for (int i = lo; i < hi; i++) {
        int d = g_deg[i];
        g_off[i] = run;
        run += d;
        g_inv[i] = 1.0f / fmaxf((float)d, 1.0f);
    }
    if (t == 1023) g_off[N] = E;
}

// ---------------- fill CSR ----------------
__global__ void fill_kernel(const int* __restrict__ src,
                            const int* __restrict__ dst,
                            const float* __restrict__ ew, int E) {
    int i = blockIdx.x * blockDim.x + threadIdx.x;
    int stride = gridDim.x * blockDim.x;
    for (; i < E; i += stride) {
        int d = dst[i];
        int pos = g_off[d] + atomicAdd(&g_cur[d], 1);
        g_csr_src[pos] = src[i];
        g_csr_w[pos]   = ew[i];
    }
}

// ---------------- gather aggregation (mean folded in) ----------------
// One warp per node. feat == nullptr -> read features from g_h (layer 2).
// g_agg[n] = (sum_e w_e * feat[src_e]) * inv_deg[n]
__global__ void agg_kernel(const float* __restrict__ feat, int N) {
    const float* f = feat ? feat : g_h;
    int lane = threadIdx.x & 31;
    int warp = (blockIdx.x * blockDim.x + threadIdx.x) >> 5;
    int nwarp = (gridDim.x * blockDim.x) >> 5;
    for (int n = warp; n < N; n += nwarp) {
        int start = g_off[n];
        int end   = g_off[n + 1];
        float4 acc0 = make_float4(0.f, 0.f, 0.f, 0.f);
        float4 acc1 = make_float4(0.f, 0.f, 0.f, 0.f);
        int e = start;
        for (; e + 1 < end; e += 2) {
            int   s0 = g_csr_src[e];
            float w0 = g_csr_w[e];
            int   s1 = g_csr_src[e + 1];
            float w1 = g_csr_w[e + 1];
            float4 v0 = reinterpret_cast<const float4*>(f + (size_t)s0 * CH)[lane];
            float4 v1 = reinterpret_cast<const float4*>(f + (size_t)s1 * CH)[lane];
            acc0.x += v0.x * w0; acc0.y += v0.y * w0;
            acc0.z += v0.z * w0; acc0.w += v0.w * w0;
            acc1.x += v1.x * w1; acc1.y += v1.y * w1;
            acc1.z += v1.z * w1; acc1.w += v1.w * w1;
        }
        if (e < end) {
            int   s0 = g_csr_src[e];
            float w0 = g_csr_w[e];
            float4 v0 = reinterpret_cast<const float4*>(f + (size_t)s0 * CH)[lane];
            acc0.x += v0.x * w0; acc0.y += v0.y * w0;
            acc0.z += v0.z * w0; acc0.w += v0.w * w0;
        }
        float inv = g_inv[n];
        float4 r;
        r.x = (acc0.x + acc1.x) * inv;
        r.y = (acc0.y + acc1.y) * inv;
        r.z = (acc0.z + acc1.z) * inv;
        r.w = (acc0.w + acc1.w) * inv;
        reinterpret_cast<float4*>(g_agg + (size_t)n * CH)[lane] = r;
    }
}

// ---------------- fused GraphConv linear ----------------
// out = g_agg @ Wrel + A2 @ Wroot + bias, optional ReLU.
// A2 == nullptr -> g_h.  out_sel: 0 -> g_h, 1 -> g_z.
// W matrices are [K=128, N=128] row-major (k-major), matching jax x @ w.
#define BM 64
#define BN 128
#define BK 16
__global__ __launch_bounds__(256) void gemm_kernel(
    const float* __restrict__ A2in,
    const float* __restrict__ Wrel,
    const float* __restrict__ Wroot,
    const float* __restrict__ bias,
    int M, int relu, int out_sel) {
    const float* A2 = A2in ? A2in : g_h;
    float* out = (out_sel == 0) ? g_h : g_z;

    __shared__ float As[BM][BK];
    __shared__ float Ws[BK][BN];

    int m0 = blockIdx.x * BM;
    int t = threadIdx.x;        // 256 threads
    int tn = t & 31;            // 32 col-groups of 4
    int tm = t >> 5;            // 8 row-groups of 8

    float acc[8][4];
#pragma unroll
    for (int i = 0; i < 8; i++)
#pragma unroll
        for (int j = 0; j < 4; j++) acc[i][j] = 0.0f;

    for (int k0 = 0; k0 < 2 * CH; k0 += BK) {
        const bool first = (k0 < CH);
        const float* A = first ? g_agg : A2;
        const float* W = first ? Wrel : Wroot;
        int kc = k0 & (CH - 1);

        // load A tile: 64x16 floats, one float4 per thread
        {
            int r = t >> 2;
            int cv = (t & 3) * 4;
            int grow = m0 + r;
            float4 v = make_float4(0.f, 0.f, 0.f, 0.f);
            if (grow < M)
                v = *reinterpret_cast<const float4*>(A + (size_t)grow * CH + kc + cv);
            As[r][cv + 0] = v.x;
            As[r][cv + 1] = v.y;
            As[r][cv + 2] = v.z;
            As[r][cv + 3] = v.w;
        }
        // load W tile: 16x128 floats = 512 float4, two per thread
#pragma unroll
        for (int i = 0; i < 2; i++) {
            int idx = t + i * 256;
            int r = idx >> 5;
            int cv = (idx & 31) * 4;
            float4 w = *reinterpret_cast<const float4*>(W + (size_t)(kc + r) * CH + cv);
            *reinterpret_cast<float4*>(&Ws[r][cv]) = w;
        }
        __syncthreads();

#pragma unroll
        for (int kk = 0; kk < BK; kk++) {
            float4 b = *reinterpret_cast<float4*>(&Ws[kk][tn * 4]);
#pragma unroll
            for (int i = 0; i < 8; i++) {
                float a = As[tm * 8 + i][kk];
                acc[i][0] += a * b.x;
                acc[i][1] += a * b.y;
                acc[i][2] += a * b.z;
                acc[i][3] += a * b.w;
            }
        }
        __syncthreads();
    }

    float4 bb = *reinterpret_cast<const float4*>(bias + tn * 4);
#pragma unroll
    for (int i = 0; i < 8; i++) {
        int row = m0 + tm * 8 + i;
        if (row < M) {
            float4 r;
            r.x = acc[i][0] + bb.x;
            r.y = acc[i][1] + bb.y;
            r.z = acc[i][2] + bb.z;
            r.w = acc[i][3] + bb.w;
            if (relu) {
                r.x = fmaxf(r.x, 0.f);
                r.y = fmaxf(r.y, 0.f);
                r.z = fmaxf(r.z, 0.f);
                r.w = fmaxf(r.w, 0.f);
            }
            reinterpret_cast<float4*>(out + (size_t)row * CH)[tn] = r;
        }
    }
}

// ---------------- decoder: pair dot products ----------------
__global__ void decode_kernel(const int* __restrict__ ps,
                              const int* __restrict__ pd,
                              float* __restrict__ out, int P) {
    int lane = threadIdx.x & 31;
    int warp = (blockIdx.x * blockDim.x + threadIdx.x) >> 5;
    int nwarp = (gridDim.x * blockDim.x) >> 5;
    const float inv_scale = 0.08838834764831845f;  // 1/sqrt(128)
    for (int p = warp; p < P; p += nwarp) {
        int s = ps[p];
        int d = pd[p];
        float4 a = reinterpret_cast<const float4*>(g_z + (size_t)s * CH)[lane];
        float4 b = reinterpret_cast<const float4*>(g_z + (size_t)d * CH)[lane];
        float sum = a.x * b.x + a.y * b.y + a.z * b.z + a.w * b.w;
#pragma unroll
        for (int o = 16; o; o >>= 1) sum += __shfl_xor_sync(0xFFFFFFFFu, sum, o);
        if (lane == 0) out[p] = sum * inv_scale;
    }
}

// ---------------- launch ----------------
extern "C" void kernel_launch(void* const* d_in, const int* in_sizes, int n_in,
                              void* d_out, int out_size) {
    const float* x       = (const float*)d_in[0];
    const int*   ei      = (const int*)d_in[1];
    const float* ew      = (const float*)d_in[2];
    const int*   eli     = (const int*)d_in[3];
    const float* w1_rel  = (const float*)d_in[4];
    const float* b1_rel  = (const float*)d_in[5];
    const float* w1_root = (const float*)d_in[6];
    const float* w2_rel  = (const float*)d_in[7];
    const float* b2_rel  = (const float*)d_in[8];
    const float* w2_root = (const float*)d_in[9];
    float* out = (float*)d_out;

    const int N = in_sizes[0] / CH;
    const int E = in_sizes[2];
    const int P = in_sizes[3] / 2;

    const int* src = ei;
    const int* dst = ei + E;
    const int* ps  = eli;
    const int* pd  = eli + P;

    const int egrid = (E + 255) / 256;
    const int ngrid = (N + 255) / 256;
    const int agrid = (N * 32 + 255) / 256;   // warp per node
    const int ggrid = (N + BM - 1) / BM;

    // ---- CSR build (per launch; graph-capturable, deterministic work) ----
    zero_deg_kernel<<<ngrid, 256>>>(N);
    hist_kernel<<<egrid, 256>>>(dst, E);
    scan_kernel<<<1, 1024>>>(N, E);
    fill_kernel<<<egrid, 256>>>(src, dst, ew, E);

    // ---- layer 1 ----
    agg_kernel<<<agrid, 256>>>(x, N);
    gemm_kernel<<<ggrid, 256>>>(x, w1_rel, w1_root, b1_rel, N, /*relu=*/1, /*out=h*/0);

    // ---- layer 2 ----
    agg_kernel<<<agrid, 256>>>(nullptr, N);
    gemm_kernel<<<ggrid, 256>>>(nullptr, w2_rel, w2_root, b2_rel, N, /*relu=*/0, /*out=z*/1);

    // ---- decode ----
    decode_kernel<<<2048, 256>>>(ps, pd, out, P);
}

// round 3
// speedup vs baseline: 1.1112x; 1.1112x over previous
#include <cuda_runtime.h>
#include <cuda_bf16.h>
#include <math.h>

// Problem constants (match reference setup_inputs)
#define NN 100000      // nodes
#define NE 1600000     // edges
#define CH 128         // channels (in == hid)

// ---------------- scratch (no allocations allowed) ----------------
__device__ float g_agg[(size_t)NN * CH];
__device__ float g_h  [(size_t)NN * CH];
__device__ float g_z  [(size_t)NN * CH];
__device__ float g_inv[NN];
__device__ int   g_deg[NN];
__device__ int   g_cur[NN];
__device__ int   g_off[NN + 1];
__device__ int   g_csr_src[NE];
__device__ float g_csr_w[NE];

// ---------------- packed f32x2 helpers (sm_103a FFMA2) ----------------
__device__ __forceinline__ void ffma2(unsigned long long& d,
                                      unsigned long long a,
                                      unsigned long long b) {
    asm("fma.rn.f32x2 %0, %1, %2, %0;" : "+l"(d) : "l"(a), "l"(b));
}
__device__ __forceinline__ unsigned long long pack2(float lo, float hi) {
    unsigned long long r;
    asm("mov.b64 %0, {%1, %2};" : "=l"(r) : "f"(lo), "f"(hi));
    return r;
}

// ---------------- zero degree/cursor ----------------
__global__ void zero_deg_kernel(int n) {
    int i = blockIdx.x * blockDim.x + threadIdx.x;
    int stride = gridDim.x * blockDim.x;
    for (; i < n; i += stride) { g_deg[i] = 0; g_cur[i] = 0; }
}

// ---------------- histogram of in-degrees ----------------
__global__ void hist_kernel(const int* __restrict__ dst, int E) {
    int i = blockIdx.x * blockDim.x + threadIdx.x;
    int stride = gridDim.x * blockDim.x;
    for (; i < E; i += stride) atomicAdd(&g_deg[dst[i]], 1);
}

// ---------------- single-block exclusive scan -> offsets, inv degree ----------------
__global__ __launch_bounds__(1024) void scan_kernel(int N, int E) {
    __shared__ int sums[1024];
    int t = threadIdx.x;
    int chunk = (N + 1023) >> 10;
    int lo = t * chunk;
    int hi = min(lo + chunk, N);
    int s = 0;
    for (int i = lo; i < hi; i++) s += g_deg[i];
    sums[t] = s;
    __syncthreads();
    for (int o = 1; o < 1024; o <<= 1) {
        int v = (t >= o) ? sums[t - o] : 0;
        __syncthreads();
        sums[t] += v;
        __syncthreads();
    }
    int run = (t > 0) ? sums[t - 1] : 0;
    for (int i = lo; i < hi; i++) {
        int d = g_deg[i];
        g_off[i] = run;
        run += d;
        g_inv[i] = 1.0f / fmaxf((float)d, 1.0f);
    }
    if (t == 1023) g_off[N] = E;
}

// ---------------- fill CSR ----------------
__global__ void fill_kernel(const int* __restrict__ src,
                            const int* __restrict__ dst,
                            const float* __restrict__ ew, int E) {
    int i = blockIdx.x * blockDim.x + threadIdx.x;
    int stride = gridDim.x * blockDim.x;
    for (; i < E; i += stride) {
        int d = dst[i];
        int pos = g_off[d] + atomicAdd(&g_cur[d], 1);
        g_csr_src[pos] = src[i];
        g_csr_w[pos]   = ew[i];
    }
}

// ---------------- gather aggregation (mean folded in) ----------------
__global__ void agg_kernel(const float* __restrict__ feat, int N) {
    const float* f = feat ? feat : g_h;
    int lane = threadIdx.x & 31;
    int warp = (blockIdx.x * blockDim.x + threadIdx.x) >> 5;
    int nwarp = (gridDim.x * blockDim.x) >> 5;
    for (int n = warp; n < N; n += nwarp) {
        int start = g_off[n];
        int end   = g_off[n + 1];
        float4 acc0 = make_float4(0.f, 0.f, 0.f, 0.f);
        float4 acc1 = make_float4(0.f, 0.f, 0.f, 0.f);
        int e = start;
        for (; e + 1 < end; e += 2) {
            int   s0 = g_csr_src[e];
            float w0 = g_csr_w[e];
            int   s1 = g_csr_src[e + 1];
            float w1 = g_csr_w[e + 1];
            float4 v0 = reinterpret_cast<const float4*>(f + (size_t)s0 * CH)[lane];
            float4 v1 = reinterpret_cast<const float4*>(f + (size_t)s1 * CH)[lane];
            acc0.x += v0.x * w0; acc0.y += v0.y * w0;
            acc0.z += v0.z * w0; acc0.w += v0.w * w0;
            acc1.x += v1.x * w1; acc1.y += v1.y * w1;
            acc1.z += v1.z * w1; acc1.w += v1.w * w1;
        }
        if (e < end) {
            int   s0 = g_csr_src[e];
            float w0 = g_csr_w[e];
            float4 v0 = reinterpret_cast<const float4*>(f + (size_t)s0 * CH)[lane];
            acc0.x += v0.x * w0; acc0.y += v0.y * w0;
            acc0.z += v0.z * w0; acc0.w += v0.w * w0;
        }
        float inv = g_inv[n];
        float4 r;
        r.x = (acc0.x + acc1.x) * inv;
        r.y = (acc0.y + acc1.y) * inv;
        r.z = (acc0.z + acc1.z) * inv;
        r.w = (acc0.w + acc1.w) * inv;
        reinterpret_cast<float4*>(g_agg + (size_t)n * CH)[lane] = r;
    }
}

// ---------------- fused GraphConv linear (packed f32x2 FMA) ----------------
// out = g_agg @ Wrel + A2 @ Wroot + bias, optional ReLU.
// A2 == nullptr -> g_h.  out_sel: 0 -> g_h, 1 -> g_z.
#define BM 64
#define BN 128
#define BK 16
__global__ __launch_bounds__(256) void gemm_kernel(
    const float* __restrict__ A2in,
    const float* __restrict__ Wrel,
    const float* __restrict__ Wroot,
    const float* __restrict__ bias,
    int M, int relu, int out_sel) {
    const float* A2 = A2in ? A2in : g_h;
    float* out = (out_sel == 0) ? g_h : g_z;

    __shared__ float AsT[BK][BM];   // k-major: adjacent rows contiguous
    __shared__ float Ws[BK][BN];

    int m0 = blockIdx.x * BM;
    int t = threadIdx.x;        // 256 threads
    int tn = t & 31;            // 32 col-groups of 4
    int tm = t >> 5;            // 8 row-groups of 8 (as 4 packed pairs)

    // acc[rp][c]: packed {row 2rp, row 2rp+1} for column tn*4+c
    unsigned long long acc[4][4];
#pragma unroll
    for (int i = 0; i < 4; i++)
#pragma unroll
        for (int j = 0; j < 4; j++) acc[i][j] = 0ULL;

    for (int k0 = 0; k0 < 2 * CH; k0 += BK) {
        const bool first = (k0 < CH);
        const float* A = first ? g_agg : A2;
        const float* W = first ? Wrel : Wroot;
        int kc = k0 & (CH - 1);

        // load A tile 64x16 -> transposed AsT[k][row]
        {
            int r = t >> 2;
            int cv = (t & 3) * 4;
            int grow = m0 + r;
            float4 v = make_float4(0.f, 0.f, 0.f, 0.f);
            if (grow < M)
                v = *reinterpret_cast<const float4*>(A + (size_t)grow * CH + kc + cv);
            AsT[cv + 0][r] = v.x;
            AsT[cv + 1][r] = v.y;
            AsT[cv + 2][r] = v.z;
            AsT[cv + 3][r] = v.w;
        }
        // load W tile: 16x128 floats = 512 float4, two per thread
#pragma unroll
        for (int i = 0; i < 2; i++) {
            int idx = t + i * 256;
            int r = idx >> 5;
            int cv = (idx & 31) * 4;
            float4 w = *reinterpret_cast<const float4*>(W + (size_t)(kc + r) * CH + cv);
            *reinterpret_cast<float4*>(&Ws[r][cv]) = w;
        }
        __syncthreads();

#pragma unroll
        for (int kk = 0; kk < BK; kk++) {
            float4 b = *reinterpret_cast<float4*>(&Ws[kk][tn * 4]);
            unsigned long long bb0 = pack2(b.x, b.x);
            unsigned long long bb1 = pack2(b.y, b.y);
            unsigned long long bb2 = pack2(b.z, b.z);
            unsigned long long bb3 = pack2(b.w, b.w);
#pragma unroll
            for (int rp = 0; rp < 4; rp++) {
                // broadcast LDS.64: packed {a_row2rp, a_row2rp+1}
                unsigned long long aa =
                    *reinterpret_cast<const unsigned long long*>(&AsT[kk][tm * 8 + rp * 2]);
                ffma2(acc[rp][0], aa, bb0);
                ffma2(acc[rp][1], aa, bb1);
                ffma2(acc[rp][2], aa, bb2);
                ffma2(acc[rp][3], aa, bb3);
            }
        }
        __syncthreads();
    }

    float4 bb = *reinterpret_cast<const float4*>(bias + tn * 4);
#pragma unroll
    for (int rp = 0; rp < 4; rp++) {
        float2 c0 = *reinterpret_cast<float2*>(&acc[rp][0]);
        float2 c1 = *reinterpret_cast<float2*>(&acc[rp][1]);
        float2 c2 = *reinterpret_cast<float2*>(&acc[rp][2]);
        float2 c3 = *reinterpret_cast<float2*>(&acc[rp][3]);
        int row0 = m0 + tm * 8 + rp * 2;
#pragma unroll
        for (int h = 0; h < 2; h++) {
            int row = row0 + h;
            if (row < M) {
                float4 r;
                r.x = (h ? c0.y : c0.x) + bb.x;
                r.y = (h ? c1.y : c1.x) + bb.y;
                r.z = (h ? c2.y : c2.x) + bb.z;
                r.w = (h ? c3.y : c3.x) + bb.w;
                if (relu) {
                    r.x = fmaxf(r.x, 0.f);
                    r.y = fmaxf(r.y, 0.f);
                    r.z = fmaxf(r.z, 0.f);
                    r.w = fmaxf(r.w, 0.f);
                }
                reinterpret_cast<float4*>(out + (size_t)row * CH)[tn] = r;
            }
        }
    }
}

// ---------------- decoder: pair dot products ----------------
__global__ void decode_kernel(const int* __restrict__ ps,
                              const int* __restrict__ pd,
                              float* __restrict__ out, int P) {
    int lane = threadIdx.x & 31;
    int warp = (blockIdx.x * blockDim.x + threadIdx.x) >> 5;
    int nwarp = (gridDim.x * blockDim.x) >> 5;
    const float inv_scale = 0.08838834764831845f;  // 1/sqrt(128)
    for (int p = warp; p < P; p += nwarp) {
        int s = ps[p];
        int d = pd[p];
        float4 a = reinterpret_cast<const float4*>(g_z + (size_t)s * CH)[lane];
        float4 b = reinterpret_cast<const float4*>(g_z + (size_t)d * CH)[lane];
        float sum = a.x * b.x + a.y * b.y + a.z * b.z + a.w * b.w;
#pragma unroll
        for (int o = 16; o; o >>= 1) sum += __shfl_xor_sync(0xFFFFFFFFu, sum, o);
        if (lane == 0) out[p] = sum * inv_scale;
    }
}

// ---------------- launch ----------------
extern "C" void kernel_launch(void* const* d_in, const int* in_sizes, int n_in,
                              void* d_out, int out_size) {
    const float* x       = (const float*)d_in[0];
    const int*   ei      = (const int*)d_in[1];
    const float* ew      = (const float*)d_in[2];
    const int*   eli     = (const int*)d_in[3];
    const float* w1_rel  = (const float*)d_in[4];
    const float* b1_rel  = (const float*)d_in[5];
    const float* w1_root = (const float*)d_in[6];
    const float* w2_rel  = (const float*)d_in[7];
    const float* b2_rel  = (const float*)d_in[8];
    const float* w2_root = (const float*)d_in[9];
    float* out = (float*)d_out;

    const int N = in_sizes[0] / CH;
    const int E = in_sizes[2];
    const int P = in_sizes[3] / 2;

    const int* src = ei;
    const int* dst = ei + E;
    const int* ps  = eli;
    const int* pd  = eli + P;

    const int egrid = (E + 255) / 256;
    const int ngrid = (N + 255) / 256;
    const int agrid = (N * 32 + 255) / 256;   // warp per node
    const int ggrid = (N + BM - 1) / BM;

    // ---- CSR build ----
    zero_deg_kernel<<<ngrid, 256>>>(N);
    hist_kernel<<<egrid, 256>>>(dst, E);
    scan_kernel<<<1, 1024>>>(N, E);
    fill_kernel<<<egrid, 256>>>(src, dst, ew, E);

    // ---- layer 1 ----
    agg_kernel<<<agrid, 256>>>(x, N);
    gemm_kernel<<<ggrid, 256>>>(x, w1_rel, w1_root, b1_rel, N, /*relu=*/1, /*out=h*/0);

    // ---- layer 2 ----
    agg_kernel<<<agrid, 256>>>(nullptr, N);
    gemm_kernel<<<ggrid, 256>>>(nullptr, w2_rel, w2_root, b2_rel, N, /*relu=*/0, /*out=z*/1);

    // ---- decode ----
    decode_kernel<<<2048, 256>>>(ps, pd, out, P);
}

// round 12
// speedup vs baseline: 1.3398x; 1.2057x over previous
#include <cuda_runtime.h>
#include <cuda_bf16.h>
#include <math.h>
#include <cstdint>

// Problem constants (match reference setup_inputs)
#define NN 100000      // nodes
#define NE 1600000     // edges
#define CH 128         // channels (in == hid)

#define BST 136        // padded bf16 row stride for SMEM tiles (bank-conflict-free)

// ---------------- scratch (no allocations allowed) ----------------
__device__ float g_agg[(size_t)NN * CH];
__device__ float g_h  [(size_t)NN * CH];
__device__ float g_z  [(size_t)NN * CH];
__device__ float g_inv[NN];
__device__ int   g_deg[NN];
__device__ int   g_cur[NN];
__device__ int   g_off[NN + 1];
__device__ int   g_csr_src[NE];
__device__ float g_csr_w[NE];
// Pre-transposed+split bf16 B tiles, padded [n][BST]:
// [matrix (w1_rel,w1_root,w2_rel,w2_root)][hi/lo][128*BST]
__device__ __nv_bfloat16 g_bimg[4][2][128 * BST];

// ---------------- SMEM layout for tgemm (bytes) ----------------
#define SM2_BIAS 0                       // 128 f32 = 512 B
#define SM2_AHI  512
#define SM2_ALO  (SM2_AHI + 128 * BST * 2)   // 512 + 34816
#define SM2_BHI  (SM2_ALO + 128 * BST * 2)
#define SM2_BLO  (SM2_BHI + 128 * BST * 2)
#define SM2_TOTAL (SM2_BLO + 128 * BST * 2)  // 139776 B

// ---------------- bf16 mma.sync (baseline PTX, valid at compute_103) ----------------
__device__ __forceinline__ void mma_bf16(float* c, const uint32_t* a, const uint32_t* b) {
    asm volatile(
        "mma.sync.aligned.m16n8k16.row.col.f32.bf16.bf16.f32 "
        "{%0,%1,%2,%3}, {%4,%5,%6,%7}, {%8,%9}, {%0,%1,%2,%3};"
        : "+f"(c[0]), "+f"(c[1]), "+f"(c[2]), "+f"(c[3])
        : "r"(a[0]), "r"(a[1]), "r"(a[2]), "r"(a[3]), "r"(b[0]), "r"(b[1]));
}

// ---------------- prep: transpose+split weights into padded [n][k] bf16 tiles ----------------
__global__ void prep_b_kernel(const float* __restrict__ w1_rel, const float* __restrict__ w1_root,
                              const float* __restrict__ w2_rel, const float* __restrict__ w2_root) {
    int idx = blockIdx.x * blockDim.x + threadIdx.x;
    if (idx >= 4 * 128 * 128) return;
    int m = idx >> 14;
    int r = idx & 16383;
    int n = r >> 7;       // output col -> B row
    int k = r & 127;      // K index -> B col
    const float* W = (m == 0) ? w1_rel : (m == 1) ? w1_root : (m == 2) ? w2_rel : w2_root;
    float w = W[k * 128 + n];          // W is [K][N] row-major; B[n][k] = W[k][n]
    __nv_bfloat16 h = __float2bfloat16(w);
    float lo = w - __bfloat162float(h);
    g_bimg[m][0][n * BST + k] = h;
    g_bimg[m][1][n * BST + k] = __float2bfloat16(lo);
}

// ---------------- tensor-core GraphConv linear (mma.sync bf16 2-split) ----------------
// out = g_agg @ Wrel + A2 @ Wroot + bias (+ReLU)
__global__ __launch_bounds__(256) void tgemm_kernel(
    const float* __restrict__ A2in, const float* __restrict__ bias,
    int M, int relu, int out_sel, int layer) {
    extern __shared__ char smem[];
    const float* A2 = A2in ? A2in : g_h;
    float* outg = (out_sel == 0) ? g_h : g_z;
    int tid = threadIdx.x;
    int wid = tid >> 5;
    int lane = tid & 31;
    int g = lane >> 2;        // group 0..7
    int tig = lane & 3;       // thread-in-group
    int m0 = blockIdx.x * 128;
    int wm = (wid & 3) * 32;  // warp m offset
    int wn = (wid >> 2) * 64; // warp n offset

    __nv_bfloat16* Ah = (__nv_bfloat16*)(smem + SM2_AHI);
    __nv_bfloat16* Al = (__nv_bfloat16*)(smem + SM2_ALO);
    __nv_bfloat16* Bh = (__nv_bfloat16*)(smem + SM2_BHI);
    __nv_bfloat16* Bl = (__nv_bfloat16*)(smem + SM2_BLO);
    float* bs = (float*)(smem + SM2_BIAS);

    if (tid < 128) bs[tid] = bias[tid];

    float acc[2][8][4];
#pragma unroll
    for (int i = 0; i < 2; i++)
#pragma unroll
        for (int j = 0; j < 8; j++)
#pragma unroll
            for (int q = 0; q < 4; q++) acc[i][j][q] = 0.0f;

    for (int kh = 0; kh < 2; kh++) {
        const float* S = (kh == 0) ? g_agg : A2;
        if (kh == 1) __syncthreads();   // all warps done reading kh=0 tiles
        // ---- stage A: fp32 -> bf16 hi/lo, row-major padded ----
#pragma unroll
        for (int it = 0; it < 8; it++) {
            int gg = it * 256 + tid;       // granule 0..2047 (8 cols each)
            int row = gg >> 4;
            int col = (gg & 15) * 8;
            float4 v0 = make_float4(0.f, 0.f, 0.f, 0.f);
            float4 v1 = make_float4(0.f, 0.f, 0.f, 0.f);
            int grow = m0 + row;
            if (grow < M) {
                const float* p = S + (size_t)grow * CH + col;
                v0 = reinterpret_cast<const float4*>(p)[0];
                v1 = reinterpret_cast<const float4*>(p)[1];
            }
            float a[8] = {v0.x, v0.y, v0.z, v0.w, v1.x, v1.y, v1.z, v1.w};
            uint32_t hu[4], lu[4];
#pragma unroll
            for (int j = 0; j < 4; j++) {
                __nv_bfloat162 hh = __floats2bfloat162_rn(a[2 * j], a[2 * j + 1]);
                float2 hf = __bfloat1622float2(hh);
                __nv_bfloat162 ll = __floats2bfloat162_rn(a[2 * j] - hf.x, a[2 * j + 1] - hf.y);
                hu[j] = *reinterpret_cast<uint32_t*>(&hh);
                lu[j] = *reinterpret_cast<uint32_t*>(&ll);
            }
            int off = row * BST + col;     // bf16 index; byte offset mult of 16
            *reinterpret_cast<uint4*>(Ah + off) = make_uint4(hu[0], hu[1], hu[2], hu[3]);
            *reinterpret_cast<uint4*>(Al + off) = make_uint4(lu[0], lu[1], lu[2], lu[3]);
        }
        // ---- stage B: raw copy of prepped tiles (128*BST bf16 = 2176 uint4) ----
        {
            const uint4* shi = reinterpret_cast<const uint4*>(g_bimg[layer * 2 + kh][0]);
            const uint4* slo = reinterpret_cast<const uint4*>(g_bimg[layer * 2 + kh][1]);
            uint4* dhi = reinterpret_cast<uint4*>(Bh);
            uint4* dlo = reinterpret_cast<uint4*>(Bl);
            for (int i = tid; i < 128 * BST / 8; i += 256) {
                dhi[i] = shi[i];
                dlo[i] = slo[i];
            }
        }
        __syncthreads();

        // ---- compute: 3 splits x 8 ksteps x (2m x 8n) mma ----
#pragma unroll
        for (int sp = 0; sp < 3; sp++) {
            const __nv_bfloat16* As = (sp == 2) ? Al : Ah;
            const __nv_bfloat16* Bs = (sp == 1) ? Bl : Bh;
#pragma unroll
            for (int ks = 0; ks < 8; ks++) {
                int k0 = ks * 16;
                uint32_t afr[2][4];
#pragma unroll
                for (int mi = 0; mi < 2; mi++) {
                    int rb = wm + mi * 16;
                    const __nv_bfloat16* p0 = As + (rb + g) * BST + k0 + tig * 2;
                    const __nv_bfloat16* p1 = As + (rb + g + 8) * BST + k0 + tig * 2;
                    afr[mi][0] = *reinterpret_cast<const uint32_t*>(p0);
                    afr[mi][1] = *reinterpret_cast<const uint32_t*>(p1);
                    afr[mi][2] = *reinterpret_cast<const uint32_t*>(p0 + 8);
                    afr[mi][3] = *reinterpret_cast<const uint32_t*>(p1 + 8);
                }
                uint32_t bfr[8][2];
#pragma unroll
                for (int ni = 0; ni < 8; ni++) {
                    const __nv_bfloat16* p = Bs + (wn + ni * 8 + g) * BST + k0 + tig * 2;
                    bfr[ni][0] = *reinterpret_cast<const uint32_t*>(p);
                    bfr[ni][1] = *reinterpret_cast<const uint32_t*>(p + 8);
                }
#pragma unroll
                for (int mi = 0; mi < 2; mi++)
#pragma unroll
                    for (int ni = 0; ni < 8; ni++)
                        mma_bf16(acc[mi][ni], afr[mi], bfr[ni]);
            }
        }
    }

    // ---- epilogue: bias (+ReLU), direct STG (32B sectors per row-group) ----
#pragma unroll
    for (int mi = 0; mi < 2; mi++) {
        int rb = m0 + wm + mi * 16;
#pragma unroll
        for (int ni = 0; ni < 8; ni++) {
            int col = wn + ni * 8 + tig * 2;
            float b0 = bs[col], b1 = bs[col + 1];
            int r0 = rb + g, r1 = rb + g + 8;
            float2 v;
            if (r0 < M) {
                v.x = acc[mi][ni][0] + b0;
                v.y = acc[mi][ni][1] + b1;
                if (relu) { v.x = fmaxf(v.x, 0.f); v.y = fmaxf(v.y, 0.f); }
                *reinterpret_cast<float2*>(outg + (size_t)r0 * CH + col) = v;
            }
            if (r1 < M) {
                v.x = acc[mi][ni][2] + b0;
                v.y = acc[mi][ni][3] + b1;
                if (relu) { v.x = fmaxf(v.x, 0.f); v.y = fmaxf(v.y, 0.f); }
                *reinterpret_cast<float2*>(outg + (size_t)r1 * CH + col) = v;
            }
        }
    }
}

// ---------------- CSR build ----------------
__global__ void zero_deg_kernel(int n) {
    int i = blockIdx.x * blockDim.x + threadIdx.x;
    int stride = gridDim.x * blockDim.x;
    for (; i < n; i += stride) { g_deg[i] = 0; g_cur[i] = 0; }
}
__global__ void hist_kernel(const int* __restrict__ dst, int E) {
    int i = blockIdx.x * blockDim.x + threadIdx.x;
    int stride = gridDim.x * blockDim.x;
    for (; i < E; i += stride) atomicAdd(&g_deg[dst[i]], 1);
}
__global__ __launch_bounds__(1024) void scan_kernel(int N, int E) {
    __shared__ int sums[1024];
    int t = threadIdx.x;
    int chunk = (N + 1023) >> 10;
    int lo = t * chunk;
    int hi = min(lo + chunk, N);
    int s = 0;
    for (int i = lo; i < hi; i++) s += g_deg[i];
    sums[t] = s;
    __syncthreads();
    for (int o = 1; o < 1024; o <<= 1) {
        int v = (t >= o) ? sums[t - o] : 0;
        __syncthreads();
        sums[t] += v;
        __syncthreads();
    }
    int run = (t > 0) ? sums[t - 1] : 0;
    for (int i = lo; i < hi; i++) {
        int d = g_deg[i];
        g_off[i] = run;
        run += d;
        g_inv[i] = 1.0f / fmaxf((float)d, 1.0f);
    }
    if (t == 1023) g_off[N] = E;
}
__global__ void fill_kernel(const int* __restrict__ src,
                            const int* __restrict__ dst,
                            const float* __restrict__ ew, int E) {
    int i = blockIdx.x * blockDim.x + threadIdx.x;
    int stride = gridDim.x * blockDim.x;
    for (; i < E; i += stride) {
        int d = dst[i];
        int pos = g_off[d] + atomicAdd(&g_cur[d], 1);
        g_csr_src[pos] = src[i];
        g_csr_w[pos]   = ew[i];
    }
}

// ---------------- gather aggregation (mean folded in) ----------------
__global__ void agg_kernel(const float* __restrict__ feat, int N) {
    const float* f = feat ? feat : g_h;
    int lane = threadIdx.x & 31;
    int warp = (blockIdx.x * blockDim.x + threadIdx.x) >> 5;
    int nwarp = (gridDim.x * blockDim.x) >> 5;
    for (int n = warp; n < N; n += nwarp) {
        int start = g_off[n];
        int end   = g_off[n + 1];
        float4 acc0 = make_float4(0.f, 0.f, 0.f, 0.f);
        float4 acc1 = make_float4(0.f, 0.f, 0.f, 0.f);
        int e = start;
        for (; e + 1 < end; e += 2) {
            int   s0 = g_csr_src[e];
            float w0 = g_csr_w[e];
            int   s1 = g_csr_src[e + 1];
            float w1 = g_csr_w[e + 1];
            float4 v0 = reinterpret_cast<const float4*>(f + (size_t)s0 * CH)[lane];
            float4 v1 = reinterpret_cast<const float4*>(f + (size_t)s1 * CH)[lane];
            acc0.x += v0.x * w0; acc0.y += v0.y * w0;
            acc0.z += v0.z * w0; acc0.w += v0.w * w0;
            acc1.x += v1.x * w1; acc1.y += v1.y * w1;
            acc1.z += v1.z * w1; acc1.w += v1.w * w1;
        }
        if (e < end) {
            int   s0 = g_csr_src[e];
            float w0 = g_csr_w[e];
            float4 v0 = reinterpret_cast<const float4*>(f + (size_t)s0 * CH)[lane];
            acc0.x += v0.x * w0; acc0.y += v0.y * w0;
            acc0.z += v0.z * w0; acc0.w += v0.w * w0;
        }
        float inv = g_inv[n];
        float4 r;
        r.x = (acc0.x + acc1.x) * inv;
        r.y = (acc0.y + acc1.y) * inv;
        r.z = (acc0.z + acc1.z) * inv;
        r.w = (acc0.w + acc1.w) * inv;
        reinterpret_cast<float4*>(g_agg + (size_t)n * CH)[lane] = r;
    }
}

// ---------------- decoder: pair dot products ----------------
__global__ void decode_kernel(const int* __restrict__ ps,
                              const int* __restrict__ pd,
                              float* __restrict__ out, int P) {
    int lane = threadIdx.x & 31;
    int warp = (blockIdx.x * blockDim.x + threadIdx.x) >> 5;
    int nwarp = (gridDim.x * blockDim.x) >> 5;
    const float inv_scale = 0.08838834764831845f;  // 1/sqrt(128)
    for (int p = warp; p < P; p += nwarp) {
        int s = ps[p];
        int d = pd[p];
        float4 a = reinterpret_cast<const float4*>(g_z + (size_t)s * CH)[lane];
        float4 b = reinterpret_cast<const float4*>(g_z + (size_t)d * CH)[lane];
        float sum = a.x * b.x + a.y * b.y + a.z * b.z + a.w * b.w;
#pragma unroll
        for (int o = 16; o; o >>= 1) sum += __shfl_xor_sync(0xFFFFFFFFu, sum, o);
        if (lane == 0) out[p] = sum * inv_scale;
    }
}

// ---------------- launch ----------------
extern "C" void kernel_launch(void* const* d_in, const int* in_sizes, int n_in,
                              void* d_out, int out_size) {
    const float* x       = (const float*)d_in[0];
    const int*   ei      = (const int*)d_in[1];
    const float* ew      = (const float*)d_in[2];
    const int*   eli     = (const int*)d_in[3];
    const float* w1_rel  = (const float*)d_in[4];
    const float* b1_rel  = (const float*)d_in[5];
    const float* w1_root = (const float*)d_in[6];
    const float* w2_rel  = (const float*)d_in[7];
    const float* b2_rel  = (const float*)d_in[8];
    const float* w2_root = (const float*)d_in[9];
    float* out = (float*)d_out;

    const int N = in_sizes[0] / CH;
    const int E = in_sizes[2];
    const int P = in_sizes[3] / 2;

    const int* src = ei;
    const int* dst = ei + E;
    const int* ps  = eli;
    const int* pd  = eli + P;

    const int egrid = (E + 255) / 256;
    const int ngrid = (N + 255) / 256;
    const int agrid = (N * 32 + 255) / 256;
    const int tgrid = (N + 127) / 128;

    cudaFuncSetAttribute(tgemm_kernel, cudaFuncAttributeMaxDynamicSharedMemorySize, SM2_TOTAL);

    // ---- weight prep + CSR build ----
    prep_b_kernel<<<(4 * 128 * 128 + 255) / 256, 256>>>(w1_rel, w1_root, w2_rel, w2_root);
    zero_deg_kernel<<<ngrid, 256>>>(N);
    hist_kernel<<<egrid, 256>>>(dst, E);
    scan_kernel<<<1, 1024>>>(N, E);
    fill_kernel<<<egrid, 256>>>(src, dst, ew, E);

    // ---- layer 1 ----
    agg_kernel<<<agrid, 256>>>(x, N);
    tgemm_kernel<<<tgrid, 256, SM2_TOTAL>>>(x, b1_rel, N, /*relu=*/1, /*out=h*/0, /*layer=*/0);

    // ---- layer 2 ----
    agg_kernel<<<agrid, 256>>>(nullptr, N);
    tgemm_kernel<<<tgrid, 256, SM2_TOTAL>>>(nullptr, b2_rel, N, /*relu=*/0, /*out=z*/1, /*layer=*/1);

    // ---- decode ----
    decode_kernel<<<2048, 256>>>(ps, pd, out, P);
}

// round 13
// speedup vs baseline: 1.9304x; 1.4409x over previous
#include <cuda_runtime.h>
#include <cuda_bf16.h>
#include <math.h>
#include <cstdint>

// Problem constants (match reference setup_inputs)
#define NN 100000      // nodes
#define NE 1600000     // edges
#define CH 128         // channels (in == hid)

#define BST 136        // padded bf16 row stride for SMEM tiles (bank-conflict-free)
#define SCAN_B 1024    // scan block size
#define MAX_BLKS 128   // >= ceil(NN/SCAN_B)

// ---------------- scratch (no allocations allowed) ----------------
__device__ float g_agg[(size_t)NN * CH];
__device__ float g_h  [(size_t)NN * CH];
__device__ float g_z  [(size_t)NN * CH];
__device__ float g_inv[NN];
__device__ int   g_deg[NN];
__device__ int   g_cur[NN];
__device__ int   g_off[NN + 1];
__device__ int   g_bsum[MAX_BLKS];
__device__ int   g_boff[MAX_BLKS];
__device__ int   g_csr_src[NE];
__device__ float g_csr_w[NE];
// Pre-transposed+split bf16 B tiles, padded [n][BST]:
// [matrix (w1_rel,w1_root,w2_rel,w2_root)][hi/lo][128*BST]
__device__ __nv_bfloat16 g_bimg[4][2][128 * BST];

// ---------------- SMEM layout for tgemm (bytes) ----------------
#define SM2_BIAS 0                       // 128 f32 = 512 B
#define SM2_AHI  512
#define SM2_ALO  (SM2_AHI + 128 * BST * 2)   // 512 + 34816
#define SM2_BHI  (SM2_ALO + 128 * BST * 2)
#define SM2_BLO  (SM2_BHI + 128 * BST * 2)
#define SM2_TOTAL (SM2_BLO + 128 * BST * 2)  // 139776 B

// ---------------- bf16 mma.sync (baseline PTX, valid at compute_103) ----------------
__device__ __forceinline__ void mma_bf16(float* c, const uint32_t* a, const uint32_t* b) {
    asm volatile(
        "mma.sync.aligned.m16n8k16.row.col.f32.bf16.bf16.f32 "
        "{%0,%1,%2,%3}, {%4,%5,%6,%7}, {%8,%9}, {%0,%1,%2,%3};"
        : "+f"(c[0]), "+f"(c[1]), "+f"(c[2]), "+f"(c[3])
        : "r"(a[0]), "r"(a[1]), "r"(a[2]), "r"(a[3]), "r"(b[0]), "r"(b[1]));
}

// ---------------- prep: transpose+split weights into padded [n][k] bf16 tiles ----------------
__global__ void prep_b_kernel(const float* __restrict__ w1_rel, const float* __restrict__ w1_root,
                              const float* __restrict__ w2_rel, const float* __restrict__ w2_root) {
    int idx = blockIdx.x * blockDim.x + threadIdx.x;
    if (idx >= 4 * 128 * 128) return;
    int m = idx >> 14;
    int r = idx & 16383;
    int n = r >> 7;       // output col -> B row
    int k = r & 127;      // K index -> B col
    const float* W = (m == 0) ? w1_rel : (m == 1) ? w1_root : (m == 2) ? w2_rel : w2_root;
    float w = W[k * 128 + n];          // W is [K][N] row-major; B[n][k] = W[k][n]
    __nv_bfloat16 h = __float2bfloat16(w);
    float lo = w - __bfloat162float(h);
    g_bimg[m][0][n * BST + k] = h;
    g_bimg[m][1][n * BST + k] = __float2bfloat16(lo);
}

// ---------------- tensor-core GraphConv linear (mma.sync bf16 2-split) ----------------
// out = g_agg @ Wrel + A2 @ Wroot + bias (+ReLU)
__global__ __launch_bounds__(256) void tgemm_kernel(
    const float* __restrict__ A2in, const float* __restrict__ bias,
    int M, int relu, int out_sel, int layer) {
    extern __shared__ char smem[];
    const float* A2 = A2in ? A2in : g_h;
    float* outg = (out_sel == 0) ? g_h : g_z;
    int tid = threadIdx.x;
    int wid = tid >> 5;
    int lane = tid & 31;
    int g = lane >> 2;        // group 0..7
    int tig = lane & 3;       // thread-in-group
    int m0 = blockIdx.x * 128;
    int wm = (wid & 3) * 32;  // warp m offset
    int wn = (wid >> 2) * 64; // warp n offset

    __nv_bfloat16* Ah = (__nv_bfloat16*)(smem + SM2_AHI);
    __nv_bfloat16* Al = (__nv_bfloat16*)(smem + SM2_ALO);
    __nv_bfloat16* Bh = (__nv_bfloat16*)(smem + SM2_BHI);
    __nv_bfloat16* Bl = (__nv_bfloat16*)(smem + SM2_BLO);
    float* bs = (float*)(smem + SM2_BIAS);

    if (tid < 128) bs[tid] = bias[tid];

    float acc[2][8][4];
#pragma unroll
    for (int i = 0; i < 2; i++)
#pragma unroll
        for (int j = 0; j < 8; j++)
#pragma unroll
            for (int q = 0; q < 4; q++) acc[i][j][q] = 0.0f;

    for (int kh = 0; kh < 2; kh++) {
        const float* S = (kh == 0) ? g_agg : A2;
        if (kh == 1) __syncthreads();   // all warps done reading kh=0 tiles
        // ---- stage A: fp32 -> bf16 hi/lo, row-major padded ----
#pragma unroll
        for (int it = 0; it < 8; it++) {
            int gg = it * 256 + tid;       // granule 0..2047 (8 cols each)
            int row = gg >> 4;
            int col = (gg & 15) * 8;
            float4 v0 = make_float4(0.f, 0.f, 0.f, 0.f);
            float4 v1 = make_float4(0.f, 0.f, 0.f, 0.f);
            int grow = m0 + row;
            if (grow < M) {
                const float* p = S + (size_t)grow * CH + col;
                v0 = reinterpret_cast<const float4*>(p)[0];
                v1 = reinterpret_cast<const float4*>(p)[1];
            }
            float a[8] = {v0.x, v0.y, v0.z, v0.w, v1.x, v1.y, v1.z, v1.w};
            uint32_t hu[4], lu[4];
#pragma unroll
            for (int j = 0; j < 4; j++) {
                __nv_bfloat162 hh = __floats2bfloat162_rn(a[2 * j], a[2 * j + 1]);
                float2 hf = __bfloat1622float2(hh);
                __nv_bfloat162 ll = __floats2bfloat162_rn(a[2 * j] - hf.x, a[2 * j + 1] - hf.y);
                hu[j] = *reinterpret_cast<uint32_t*>(&hh);
                lu[j] = *reinterpret_cast<uint32_t*>(&ll);
            }
            int off = row * BST + col;     // bf16 index; byte offset mult of 16
            *reinterpret_cast<uint4*>(Ah + off) = make_uint4(hu[0], hu[1], hu[2], hu[3]);
            *reinterpret_cast<uint4*>(Al + off) = make_uint4(lu[0], lu[1], lu[2], lu[3]);
        }
        // ---- stage B: raw copy of prepped tiles (128*BST bf16 = 2176 uint4) ----
        {
            const uint4* shi = reinterpret_cast<const uint4*>(g_bimg[layer * 2 + kh][0]);
            const uint4* slo = reinterpret_cast<const uint4*>(g_bimg[layer * 2 + kh][1]);
            uint4* dhi = reinterpret_cast<uint4*>(Bh);
            uint4* dlo = reinterpret_cast<uint4*>(Bl);
            for (int i = tid; i < 128 * BST / 8; i += 256) {
                dhi[i] = shi[i];
                dlo[i] = slo[i];
            }
        }
        __syncthreads();

        // ---- compute: 3 splits x 8 ksteps x (2m x 8n) mma ----
#pragma unroll
        for (int sp = 0; sp < 3; sp++) {
            const __nv_bfloat16* As = (sp == 2) ? Al : Ah;
            const __nv_bfloat16* Bs = (sp == 1) ? Bl : Bh;
#pragma unroll
            for (int ks = 0; ks < 8; ks++) {
                int k0 = ks * 16;
                uint32_t afr[2][4];
#pragma unroll
                for (int mi = 0; mi < 2; mi++) {
                    int rb = wm + mi * 16;
                    const __nv_bfloat16* p0 = As + (rb + g) * BST + k0 + tig * 2;
                    const __nv_bfloat16* p1 = As + (rb + g + 8) * BST + k0 + tig * 2;
                    afr[mi][0] = *reinterpret_cast<const uint32_t*>(p0);
                    afr[mi][1] = *reinterpret_cast<const uint32_t*>(p1);
                    afr[mi][2] = *reinterpret_cast<const uint32_t*>(p0 + 8);
                    afr[mi][3] = *reinterpret_cast<const uint32_t*>(p1 + 8);
                }
                uint32_t bfr[8][2];
#pragma unroll
                for (int ni = 0; ni < 8; ni++) {
                    const __nv_bfloat16* p = Bs + (wn + ni * 8 + g) * BST + k0 + tig * 2;
                    bfr[ni][0] = *reinterpret_cast<const uint32_t*>(p);
                    bfr[ni][1] = *reinterpret_cast<const uint32_t*>(p + 8);
                }
#pragma unroll
                for (int mi = 0; mi < 2; mi++)
#pragma unroll
                    for (int ni = 0; ni < 8; ni++)
                        mma_bf16(acc[mi][ni], afr[mi], bfr[ni]);
            }
        }
    }

    // ---- epilogue: bias (+ReLU), direct STG ----
#pragma unroll
    for (int mi = 0; mi < 2; mi++) {
        int rb = m0 + wm + mi * 16;
#pragma unroll
        for (int ni = 0; ni < 8; ni++) {
            int col = wn + ni * 8 + tig * 2;
            float b0 = bs[col], b1 = bs[col + 1];
            int r0 = rb + g, r1 = rb + g + 8;
            float2 v;
            if (r0 < M) {
                v.x = acc[mi][ni][0] + b0;
                v.y = acc[mi][ni][1] + b1;
                if (relu) { v.x = fmaxf(v.x, 0.f); v.y = fmaxf(v.y, 0.f); }
                *reinterpret_cast<float2*>(outg + (size_t)r0 * CH + col) = v;
            }
            if (r1 < M) {
                v.x = acc[mi][ni][2] + b0;
                v.y = acc[mi][ni][3] + b1;
                if (relu) { v.x = fmaxf(v.x, 0.f); v.y = fmaxf(v.y, 0.f); }
                *reinterpret_cast<float2*>(outg + (size_t)r1 * CH + col) = v;
            }
        }
    }
}

// ---------------- CSR build ----------------
__global__ void zero_deg_kernel(int n) {
    int i = blockIdx.x * blockDim.x + threadIdx.x;
    int stride = gridDim.x * blockDim.x;
    for (; i < n; i += stride) { g_deg[i] = 0; g_cur[i] = 0; }
}
__global__ void hist_kernel(const int* __restrict__ dst, int E) {
    int i = blockIdx.x * blockDim.x + threadIdx.x;
    int stride = gridDim.x * blockDim.x;
    for (; i < E; i += stride) atomicAdd(&g_deg[dst[i]], 1);
}

// ---- hierarchical scan: coalesced, ~10us total ----
// k1: per-block reduce of g_deg -> g_bsum
__global__ __launch_bounds__(SCAN_B) void reduce_kernel(int N) {
    __shared__ int sh[SCAN_B];
    int t = threadIdx.x;
    int i = blockIdx.x * SCAN_B + t;
    sh[t] = (i < N) ? g_deg[i] : 0;
    __syncthreads();
    for (int o = SCAN_B / 2; o > 0; o >>= 1) {
        if (t < o) sh[t] += sh[t + o];
        __syncthreads();
    }
    if (t == 0) g_bsum[blockIdx.x] = sh[0];
}
// k2: single small block scans the block sums (exclusive) and sets g_off[N]
__global__ __launch_bounds__(MAX_BLKS) void scan_tops_kernel(int nblk, int N, int E) {
    __shared__ int sh[MAX_BLKS];
    int t = threadIdx.x;
    sh[t] = (t < nblk) ? g_bsum[t] : 0;
    __syncthreads();
    for (int o = 1; o < MAX_BLKS; o <<= 1) {
        int v = (t >= o) ? sh[t - o] : 0;
        __syncthreads();
        sh[t] += v;
        __syncthreads();
    }
    if (t < nblk) g_boff[t] = (t > 0) ? sh[t - 1] : 0;   // exclusive
    if (t == 0) g_off[N] = E;
}
// k3: per-block exclusive scan + block offset -> g_off, g_inv
__global__ __launch_bounds__(SCAN_B) void scan_block_kernel(int N) {
    __shared__ int sh[SCAN_B];
    int t = threadIdx.x;
    int i = blockIdx.x * SCAN_B + t;
    int d = (i < N) ? g_deg[i] : 0;
    sh[t] = d;
    __syncthreads();
    for (int o = 1; o < SCAN_B; o <<= 1) {
        int v = (t >= o) ? sh[t - o] : 0;
        __syncthreads();
        sh[t] += v;
        __syncthreads();
    }
    if (i < N) {
        g_off[i] = g_boff[blockIdx.x] + sh[t] - d;       // exclusive
        g_inv[i] = 1.0f / fmaxf((float)d, 1.0f);
    }
}

__global__ void fill_kernel(const int* __restrict__ src,
                            const int* __restrict__ dst,
                            const float* __restrict__ ew, int E) {
    int i = blockIdx.x * blockDim.x + threadIdx.x;
    int stride = gridDim.x * blockDim.x;
    for (; i < E; i += stride) {
        int d = dst[i];
        int pos = g_off[d] + atomicAdd(&g_cur[d], 1);
        g_csr_src[pos] = src[i];
        g_csr_w[pos]   = ew[i];
    }
}

// ---------------- gather aggregation (mean folded in) ----------------
__global__ void agg_kernel(const float* __restrict__ feat, int N) {
    const float* f = feat ? feat : g_h;
    int lane = threadIdx.x & 31;
    int warp = (blockIdx.x * blockDim.x + threadIdx.x) >> 5;
    int nwarp = (gridDim.x * blockDim.x) >> 5;
    for (int n = warp; n < N; n += nwarp) {
        int start = g_off[n];
        int end   = g_off[n + 1];
        float4 acc0 = make_float4(0.f, 0.f, 0.f, 0.f);
        float4 acc1 = make_float4(0.f, 0.f, 0.f, 0.f);
        int e = start;
        for (; e + 1 < end; e += 2) {
            int   s0 = g_csr_src[e];
            float w0 = g_csr_w[e];
            int   s1 = g_csr_src[e + 1];
            float w1 = g_csr_w[e + 1];
            float4 v0 = reinterpret_cast<const float4*>(f + (size_t)s0 * CH)[lane];
            float4 v1 = reinterpret_cast<const float4*>(f + (size_t)s1 * CH)[lane];
            acc0.x += v0.x * w0; acc0.y += v0.y * w0;
            acc0.z += v0.z * w0; acc0.w += v0.w * w0;
            acc1.x += v1.x * w1; acc1.y += v1.y * w1;
            acc1.z += v1.z * w1; acc1.w += v1.w * w1;
        }
        if (e < end) {
            int   s0 = g_csr_src[e];
            float w0 = g_csr_w[e];
            float4 v0 = reinterpret_cast<const float4*>(f + (size_t)s0 * CH)[lane];
            acc0.x += v0.x * w0; acc0.y += v0.y * w0;
            acc0.z += v0.z * w0; acc0.w += v0.w * w0;
        }
        float inv = g_inv[n];
        float4 r;
        r.x = (acc0.x + acc1.x) * inv;
        r.y = (acc0.y + acc1.y) * inv;
        r.z = (acc0.z + acc1.z) * inv;
        r.w = (acc0.w + acc1.w) * inv;
        reinterpret_cast<float4*>(g_agg + (size_t)n * CH)[lane] = r;
    }
}

// ---------------- decoder: pair dot products ----------------
__global__ void decode_kernel(const int* __restrict__ ps,
                              const int* __restrict__ pd,
                              float* __restrict__ out, int P) {
    int lane = threadIdx.x & 31;
    int warp = (blockIdx.x * blockDim.x + threadIdx.x) >> 5;
    int nwarp = (gridDim.x * blockDim.x) >> 5;
    const float inv_scale = 0.08838834764831845f;  // 1/sqrt(128)
    for (int p = warp; p < P; p += nwarp) {
        int s = ps[p];
        int d = pd[p];
        float4 a = reinterpret_cast<const float4*>(g_z + (size_t)s * CH)[lane];
        float4 b = reinterpret_cast<const float4*>(g_z + (size_t)d * CH)[lane];
        float sum = a.x * b.x + a.y * b.y + a.z * b.z + a.w * b.w;
#pragma unroll
        for (int o = 16; o; o >>= 1) sum += __shfl_xor_sync(0xFFFFFFFFu, sum, o);
        if (lane == 0) out[p] = sum * inv_scale;
    }
}

// ---------------- launch ----------------
extern "C" void kernel_launch(void* const* d_in, const int* in_sizes, int n_in,
                              void* d_out, int out_size) {
    const float* x       = (const float*)d_in[0];
    const int*   ei      = (const int*)d_in[1];
    const float* ew      = (const float*)d_in[2];
    const int*   eli     = (const int*)d_in[3];
    const float* w1_rel  = (const float*)d_in[4];
    const float* b1_rel  = (const float*)d_in[5];
    const float* w1_root = (const float*)d_in[6];
    const float* w2_rel  = (const float*)d_in[7];
    const float* b2_rel  = (const float*)d_in[8];
    const float* w2_root = (const float*)d_in[9];
    float* out = (float*)d_out;

    const int N = in_sizes[0] / CH;
    const int E = in_sizes[2];
    const int P = in_sizes[3] / 2;

    const int* src = ei;
    const int* dst = ei + E;
    const int* ps  = eli;
    const int* pd  = eli + P;

    const int egrid = (E + 255) / 256;
    const int ngrid = (N + 255) / 256;
    const int agrid = (N * 32 + 255) / 256;
    const int tgrid = (N + 127) / 128;
    const int sblk  = (N + SCAN_B - 1) / SCAN_B;

    cudaFuncSetAttribute(tgemm_kernel, cudaFuncAttributeMaxDynamicSharedMemorySize, SM2_TOTAL);

    // ---- weight prep + CSR build ----
    prep_b_kernel<<<(4 * 128 * 128 + 255) / 256, 256>>>(w1_rel, w1_root, w2_rel, w2_root);
    zero_deg_kernel<<<ngrid, 256>>>(N);
    hist_kernel<<<egrid, 256>>>(dst, E);
    reduce_kernel<<<sblk, SCAN_B>>>(N);
    scan_tops_kernel<<<1, MAX_BLKS>>>(sblk, N, E);
    scan_block_kernel<<<sblk, SCAN_B>>>(N);
    fill_kernel<<<egrid, 256>>>(src, dst, ew, E);

    // ---- layer 1 ----
    agg_kernel<<<agrid, 256>>>(x, N);
    tgemm_kernel<<<tgrid, 256, SM2_TOTAL>>>(x, b1_rel, N, /*relu=*/1, /*out=h*/0, /*layer=*/0);

    // ---- layer 2 ----
    agg_kernel<<<agrid, 256>>>(nullptr, N);
    tgemm_kernel<<<tgrid, 256, SM2_TOTAL>>>(nullptr, b2_rel, N, /*relu=*/0, /*out=z*/1, /*layer=*/1);

    // ---- decode ----
    decode_kernel<<<2048, 256>>>(ps, pd, out, P);
}